// round 1
// baseline (speedup 1.0000x reference)
#include <cuda_runtime.h>
#include <cuda_fp16.h>
#include <stdint.h>

#define BB   512
#define TT   256
#define HH   512
#define HOR  64
#define G4   2048
#define NCTA 128
#define NTHR 256
#define SMEM_BYTES 107008

// persistent device state
__device__ __half g_wh[6][G4 * HH];   // 0:eWhh0 1:eWih1 2:eWhh1 3:dWhh0 4:dWih1 5:dWhh1 (rows permuted j*4+g)
__device__ __half g_h0[2][BB * HH];
__device__ __half g_h1[2][BB * HH];
__device__ float  g_part[32 * BB];
__device__ unsigned g_count = 0u;
__device__ volatile unsigned g_gen = 0u;

__device__ __forceinline__ void grid_bar() {
    __syncthreads();
    __threadfence();
    if (threadIdx.x == 0) {
        unsigned g = g_gen;
        if (atomicAdd(&g_count, 1u) == NCTA - 1) {
            g_count = 0u;
            __threadfence();
            g_gen = g + 1u;
        } else {
            while (g_gen == g) { __nanosleep(32); }
        }
        __threadfence();
    }
    __syncthreads();
}

__device__ __forceinline__ void cpa16(void* dst_smem, const void* src) {
    uint32_t d = (uint32_t)__cvta_generic_to_shared(dst_smem);
    asm volatile("cp.async.cg.shared.global [%0], [%1], 16;\n" :: "r"(d), "l"(src));
}

// stage one K-chunk (64) of A (128 rows of h) and W (64 rows) into smem
__device__ __forceinline__ void stage(__half* As, __half* Ws,
                                      const __half* hsrc, const __half* W,
                                      int b0, int n0, int kc, int tid) {
#pragma unroll
    for (int u = 0; u < 4; u++) {
        int i = tid + u * NTHR;          // 0..1023
        int r = i >> 3, cb = i & 7;
        cpa16(&As[r * 72 + cb * 8], &hsrc[(size_t)(b0 + r) * HH + kc + cb * 8]);
    }
#pragma unroll
    for (int u = 0; u < 2; u++) {
        int i = tid + u * NTHR;          // 0..511
        int r = i >> 3, cb = i & 7;
        cpa16(&Ws[r * 72 + cb * 8], &W[(size_t)(n0 + r) * HH + kc + cb * 8]);
    }
    asm volatile("cp.async.commit_group;\n" ::: "memory");
}

// acc += h[b0:b0+128, :] @ W[n0:n0+64, :]^T   (K = 512), fp16 mma, fp32 accum
__device__ __forceinline__ void gemm_acc(float acc[4][2][4],
                                         __half* As0, __half* As1, __half* Ws0, __half* Ws1,
                                         const __half* hsrc, const __half* W,
                                         int b0, int n0, int tid,
                                         int wm, int wn, int grp, int tig) {
    __half* Ac = As0; __half* An = As1;
    __half* Wc = Ws0; __half* Wn = Ws1;
    stage(Ac, Wc, hsrc, W, b0, n0, 0, tid);
#pragma unroll 1
    for (int c = 0; c < 8; c++) {
        asm volatile("cp.async.wait_group 0;\n" ::: "memory");
        __syncthreads();
        if (c < 7) stage(An, Wn, hsrc, W, b0, n0, (c + 1) * 64, tid);
#pragma unroll
        for (int kk = 0; kk < 64; kk += 16) {
            uint32_t bfr[2][2];
#pragma unroll
            for (int nf = 0; nf < 2; nf++) {
                const __half* bp = &Wc[(wn + nf * 8 + grp) * 72 + kk + tig * 2];
                bfr[nf][0] = *(const uint32_t*)(const void*)bp;
                bfr[nf][1] = *(const uint32_t*)(const void*)(bp + 8);
            }
#pragma unroll
            for (int mf = 0; mf < 4; mf++) {
                const __half* ap = &Ac[(wm + mf * 16 + grp) * 72 + kk + tig * 2];
                uint32_t a0 = *(const uint32_t*)(const void*)ap;
                uint32_t a1 = *(const uint32_t*)(const void*)(ap + 8 * 72);
                uint32_t a2 = *(const uint32_t*)(const void*)(ap + 8);
                uint32_t a3 = *(const uint32_t*)(const void*)(ap + 8 * 72 + 8);
#pragma unroll
                for (int nf = 0; nf < 2; nf++) {
                    asm volatile(
                        "mma.sync.aligned.m16n8k16.row.col.f32.f16.f16.f32 "
                        "{%0,%1,%2,%3},{%4,%5,%6,%7},{%8,%9},{%0,%1,%2,%3};"
                        : "+f"(acc[mf][nf][0]), "+f"(acc[mf][nf][1]),
                          "+f"(acc[mf][nf][2]), "+f"(acc[mf][nf][3])
                        : "r"(a0), "r"(a1), "r"(a2), "r"(a3),
                          "r"(bfr[nf][0]), "r"(bfr[nf][1]));
                }
            }
        }
        __half* t;
        t = Ac; Ac = An; An = t;
        t = Wc; Wc = Wn; Wn = t;
    }
}

__device__ __forceinline__ void store_gates(const float acc[4][2][4], float* gsm,
                                            int wm, int wn, int grp, int tig) {
#pragma unroll
    for (int mf = 0; mf < 4; mf++)
#pragma unroll
        for (int nf = 0; nf < 2; nf++) {
            int r = wm + mf * 16 + grp;
            int c = wn + nf * 8 + tig * 2;
            gsm[r * 68 + c]           = acc[mf][nf][0];
            gsm[r * 68 + c + 1]       = acc[mf][nf][1];
            gsm[(r + 8) * 68 + c]     = acc[mf][nf][2];
            gsm[(r + 8) * 68 + c + 1] = acc[mf][nf][3];
        }
}

__device__ __forceinline__ float sigf(float z) { return 1.f / (1.f + __expf(-z)); }

// LSTM pointwise for this CTA's 128x16 (batch x hidden) tile.
// gates in gsm with column layout jj*4 + gate (i,f,g,o). wih==nullptr -> no input term.
__device__ __forceinline__ void pointwise(const float* gsm, float* cs, __half* hdst,
                                          const float* bias, const float* wih,
                                          const float* dins, int b0, int j0, int tid) {
#pragma unroll
    for (int q = 0; q < 8; q++) {
        int idx = tid * 8 + q;
        int bl = idx >> 4, jj = idx & 15;
        int j = j0 + jj;
        float4 gv = *(const float4*)(const void*)&gsm[bl * 68 + jj * 4];
        float zi = gv.x + bias[j];
        float zf = gv.y + bias[512 + j];
        float zg = gv.z + bias[1024 + j];
        float zo = gv.w + bias[1536 + j];
        if (wih) {
            float xb = dins[bl];
            zi += xb * wih[j];
            zf += xb * wih[512 + j];
            zg += xb * wih[1024 + j];
            zo += xb * wih[1536 + j];
        }
        float iv = sigf(zi);
        float fv = sigf(zf);
        float gg = tanhf(zg);
        float ov = sigf(zo);
        float cc = fv * cs[bl * 16 + jj] + iv * gg;
        cs[bl * 16 + jj] = cc;
        float hh = ov * tanhf(cc);
        hdst[(size_t)(b0 + bl) * HH + j] = __float2half(hh);
    }
}

__global__ void __launch_bounds__(NTHR, 1)
lstm_persistent_kernel(const float* __restrict__ x,
                       const float* __restrict__ eWih0, const float* __restrict__ eWhh0,
                       const float* __restrict__ eb0,
                       const float* __restrict__ eWih1, const float* __restrict__ eWhh1,
                       const float* __restrict__ eb1,
                       const float* __restrict__ dWih0, const float* __restrict__ dWhh0,
                       const float* __restrict__ db0,
                       const float* __restrict__ dWih1, const float* __restrict__ dWhh1,
                       const float* __restrict__ db1,
                       const float* __restrict__ headW, const float* __restrict__ headb,
                       float* __restrict__ out) {
    extern __shared__ char smem_raw[];
    __half* As0 = (__half*)smem_raw;              // 128*72
    __half* As1 = As0 + 128 * 72;
    __half* Ws0 = As1 + 128 * 72;                 // 64*72
    __half* Ws1 = Ws0 + 64 * 72;
    float* gsm  = (float*)(smem_raw + 55296);     // 128*68
    float* c0s  = gsm + 128 * 68;                 // 128*16
    float* c1s  = c0s + 128 * 16;
    float* dins = c1s + 128 * 16;                 // 128

    const int tid  = threadIdx.x;
    const int cta  = blockIdx.x;
    const int mb   = cta >> 5, nc = cta & 31;
    const int b0   = mb * 128, n0 = nc * 64, j0 = nc * 16;
    const int lane = tid & 31, warp = tid >> 5;
    const int wm   = (warp >> 2) * 64, wn = (warp & 3) * 16;
    const int grp  = lane >> 2, tig = lane & 3;

    // ---- init: convert weights fp32->fp16 with gate-interleaved row permutation ----
    {
        int gtid = cta * NTHR + tid;
        const float* wsrc[6] = {eWhh0, eWih1, eWhh1, dWhh0, dWih1, dWhh1};
#pragma unroll
        for (int m = 0; m < 6; m++) {
            for (int i = gtid; i < G4 * HH; i += NCTA * NTHR) {
                int n = i >> 9, k = i & 511;
                int j = n >> 2, g = n & 3;
                g_wh[m][i] = __float2half(wsrc[m][(size_t)(g * 512 + j) * HH + k]);
            }
        }
        for (int i = gtid; i < BB * HH; i += NCTA * NTHR) {
            g_h0[0][i] = __float2half(0.f);
            g_h1[0][i] = __float2half(0.f);
        }
        for (int i = tid; i < 128 * 16; i += NTHR) { c0s[i] = 0.f; c1s[i] = 0.f; }
    }
    grid_bar();

    for (int step = 0; step < TT + HOR; step++) {
        const bool enc = step < TT;
        const int p = step & 1;
        const __half* h0r = g_h0[p];
        __half* h0w = g_h0[p ^ 1];
        const __half* h1r = g_h1[p];
        __half* h1w = g_h1[p ^ 1];
        const int s = step - TT;

        // ---------- Phase A (layer 0) ----------
        if (tid < 128) {
            float v;
            if (enc) {
                v = x[(size_t)(b0 + tid) * TT + step];
            } else if (s == 0) {
                v = x[(size_t)(b0 + tid) * TT + (TT - 1)];
            } else {
                v = headb[0];
#pragma unroll
                for (int cc = 0; cc < 32; cc++) v += __ldcg(&g_part[cc * BB + b0 + tid]);
                if (nc == 0) out[(size_t)(b0 + tid) * HOR + (s - 1)] = v;
            }
            dins[tid] = v;
        }

        float acc[4][2][4];
#pragma unroll
        for (int a = 0; a < 4; a++)
#pragma unroll
            for (int b = 0; b < 2; b++)
#pragma unroll
                for (int c = 0; c < 4; c++) acc[a][b][c] = 0.f;

        gemm_acc(acc, As0, As1, Ws0, Ws1, h0r, &g_wh[enc ? 0 : 3][0], b0, n0, tid, wm, wn, grp, tig);
        store_gates(acc, gsm, wm, wn, grp, tig);
        __syncthreads();
        pointwise(gsm, c0s, h0w, enc ? eb0 : db0, enc ? eWih0 : dWih0, dins, b0, j0, tid);
        grid_bar();

        // ---------- Phase B (layer 1) ----------
#pragma unroll
        for (int a = 0; a < 4; a++)
#pragma unroll
            for (int b = 0; b < 2; b++)
#pragma unroll
                for (int c = 0; c < 4; c++) acc[a][b][c] = 0.f;

        gemm_acc(acc, As0, As1, Ws0, Ws1, h0w, &g_wh[enc ? 1 : 4][0], b0, n0, tid, wm, wn, grp, tig);
        gemm_acc(acc, As0, As1, Ws0, Ws1, h1r, &g_wh[enc ? 2 : 5][0], b0, n0, tid, wm, wn, grp, tig);
        store_gates(acc, gsm, wm, wn, grp, tig);
        __syncthreads();
        pointwise(gsm, c1s, h1w, enc ? eb1 : db1, (const float*)0, dins, b0, j0, tid);

        if (!enc) {
            __syncthreads();
            if (tid < 128) {
                float pv = 0.f;
#pragma unroll
                for (int jj = 0; jj < 16; jj++)
                    pv += __half2float(h1w[(size_t)(b0 + tid) * HH + j0 + jj]) * headW[j0 + jj];
                g_part[nc * BB + b0 + tid] = pv;
            }
        }
        grid_bar();
    }

    // ---- epilogue: final horizon output ----
    if (nc == 0 && tid < 128) {
        float v = headb[0];
#pragma unroll
        for (int cc = 0; cc < 32; cc++) v += __ldcg(&g_part[cc * BB + b0 + tid]);
        out[(size_t)(b0 + tid) * HOR + (HOR - 1)] = v;
    }
}

extern "C" void kernel_launch(void* const* d_in, const int* in_sizes, int n_in,
                              void* d_out, int out_size) {
    cudaFuncSetAttribute(lstm_persistent_kernel,
                         cudaFuncAttributeMaxDynamicSharedMemorySize, SMEM_BYTES);
    lstm_persistent_kernel<<<NCTA, NTHR, SMEM_BYTES>>>(
        (const float*)d_in[0],
        (const float*)d_in[1], (const float*)d_in[2], (const float*)d_in[3],
        (const float*)d_in[4], (const float*)d_in[5], (const float*)d_in[6],
        (const float*)d_in[7], (const float*)d_in[8], (const float*)d_in[9],
        (const float*)d_in[10], (const float*)d_in[11], (const float*)d_in[12],
        (const float*)d_in[13], (const float*)d_in[14],
        (float*)d_out);
}

// round 2
// speedup vs baseline: 1.0962x; 1.0962x over previous
#include <cuda_runtime.h>
#include <cuda_fp16.h>
#include <stdint.h>

#define BB   512
#define TT   256
#define HH   512
#define HOR  64
#define G4   2048
#define NCTA 128
#define NTHR 512
#define A_TILE (128*72)
#define W_TILE (64*72)
#define SMEM_BYTES 162304

// persistent device state
__device__ __half g_wh[6][G4 * HH];   // 0:eWhh0 1:eWih1 2:eWhh1 3:dWhh0 4:dWih1 5:dWhh1 (rows permuted j*4+g)
__device__ __half g_h0[2][BB * HH];
__device__ __half g_h1[2][BB * HH];
__device__ float  g_part[32 * BB];
__device__ unsigned g_count = 0u;
__device__ volatile unsigned g_gen = 0u;

__device__ __forceinline__ void grid_bar() {
    __syncthreads();
    __threadfence();
    if (threadIdx.x == 0) {
        unsigned g = g_gen;
        if (atomicAdd(&g_count, 1u) == NCTA - 1) {
            g_count = 0u;
            __threadfence();
            g_gen = g + 1u;
        } else {
            while (g_gen == g) { __nanosleep(20); }
        }
        __threadfence();
    }
    __syncthreads();
}

__device__ __forceinline__ void cpa16(void* dst_smem, const void* src) {
    uint32_t d = (uint32_t)__cvta_generic_to_shared(dst_smem);
    asm volatile("cp.async.cg.shared.global [%0], [%1], 16;\n" :: "r"(d), "l"(src));
}

__device__ __forceinline__ void ldsm4(uint32_t& r0, uint32_t& r1, uint32_t& r2, uint32_t& r3,
                                      const __half* p) {
    uint32_t a = (uint32_t)__cvta_generic_to_shared(p);
    asm volatile("ldmatrix.sync.aligned.m8n8.x4.shared.b16 {%0,%1,%2,%3}, [%4];\n"
                 : "=r"(r0), "=r"(r1), "=r"(r2), "=r"(r3) : "r"(a));
}

#define MMA(d, A, B0, B1)                                                      \
    asm volatile("mma.sync.aligned.m16n8k16.row.col.f32.f16.f16.f32 "          \
                 "{%0,%1,%2,%3},{%4,%5,%6,%7},{%8,%9},{%0,%1,%2,%3};"          \
                 : "+f"(d[0]), "+f"(d[1]), "+f"(d[2]), "+f"(d[3])              \
                 : "r"(A[0]), "r"(A[1]), "r"(A[2]), "r"(A[3]), "r"(B0), "r"(B1))

// stage one K-chunk (64) of A (128 rows of h) and W (64 rows) into smem, commit group
__device__ __forceinline__ void stage_chunk(__half* Ab, __half* Wb,
                                            const __half* h, const __half* W,
                                            int b0, int n0, int kc, int tid) {
#pragma unroll
    for (int u = 0; u < 2; u++) {
        int i = tid + u * NTHR;          // 0..1023
        int r = i >> 3, cb = i & 7;
        cpa16(&Ab[r * 72 + cb * 8], &h[(size_t)(b0 + r) * HH + kc + cb * 8]);
    }
    {
        int r = tid >> 3, cb = tid & 7;  // 0..511 -> 64 rows x 8 blocks
        cpa16(&Wb[r * 72 + cb * 8], &W[(size_t)(n0 + r) * HH + kc + cb * 8]);
    }
    asm volatile("cp.async.commit_group;\n" ::: "memory");
}

// acc += h @ W^T over nch K-chunks of 64 (segment switch at chunk 8 for nch=16)
__device__ __forceinline__ void run_gemm(float acc[2][2][4],
                                         __half* Abuf, __half* Wbuf,
                                         const __half* hA, const __half* wA,
                                         const __half* hB, const __half* wB,
                                         int nch, int b0, int n0, int tid,
                                         int wm, int wn,
                                         int a_row, int a_k, int b_row, int b_k) {
#pragma unroll
    for (int s = 0; s < 3; s++) {
        const __half* h = (s < 8) ? hA : hB;
        const __half* W = (s < 8) ? wA : wB;
        stage_chunk(Abuf + (s & 3) * A_TILE, Wbuf + (s & 3) * W_TILE,
                    h, W, b0, n0, (s & 7) * 64, tid);
    }
#pragma unroll 1
    for (int ch = 0; ch < nch; ch++) {
        asm volatile("cp.async.wait_group 2;\n" ::: "memory");
        __syncthreads();
        int pf = ch + 3;
        if (pf < nch) {
            const __half* h = (pf < 8) ? hA : hB;
            const __half* W = (pf < 8) ? wA : wB;
            stage_chunk(Abuf + (pf & 3) * A_TILE, Wbuf + (pf & 3) * W_TILE,
                        h, W, b0, n0, (pf & 7) * 64, tid);
        } else {
            asm volatile("cp.async.commit_group;\n" ::: "memory");
        }
        const __half* Ac = Abuf + (ch & 3) * A_TILE;
        const __half* Wc = Wbuf + (ch & 3) * W_TILE;
#pragma unroll
        for (int kk = 0; kk < 64; kk += 16) {
            uint32_t Bf[4];
            ldsm4(Bf[0], Bf[1], Bf[2], Bf[3], &Wc[(wn + b_row) * 72 + kk + b_k]);
            uint32_t A0[4], A1[4];
            ldsm4(A0[0], A0[1], A0[2], A0[3], &Ac[(wm + a_row) * 72 + kk + a_k]);
            ldsm4(A1[0], A1[1], A1[2], A1[3], &Ac[(wm + 16 + a_row) * 72 + kk + a_k]);
            MMA(acc[0][0], A0, Bf[0], Bf[1]);
            MMA(acc[0][1], A0, Bf[2], Bf[3]);
            MMA(acc[1][0], A1, Bf[0], Bf[1]);
            MMA(acc[1][1], A1, Bf[2], Bf[3]);
        }
    }
}

__device__ __forceinline__ void store_gates(const float acc[2][2][4], float* gsm,
                                            int wm, int wn, int grp, int tig) {
#pragma unroll
    for (int mf = 0; mf < 2; mf++)
#pragma unroll
        for (int nf = 0; nf < 2; nf++) {
            int r = wm + mf * 16 + grp;
            int c = wn + nf * 8 + tig * 2;
            gsm[r * 68 + c]           = acc[mf][nf][0];
            gsm[r * 68 + c + 1]       = acc[mf][nf][1];
            gsm[(r + 8) * 68 + c]     = acc[mf][nf][2];
            gsm[(r + 8) * 68 + c + 1] = acc[mf][nf][3];
        }
}

__device__ __forceinline__ float sigf(float z) { return 1.f / (1.f + __expf(-z)); }

// LSTM pointwise for this CTA's 128x16 (batch x hidden) tile.
__device__ __forceinline__ void pointwise(const float* gsm, float* cs, __half* hdst,
                                          const float* bias, const float* wih,
                                          const float* dins, int b0, int j0, int tid) {
#pragma unroll
    for (int q = 0; q < 4; q++) {
        int idx = tid * 4 + q;
        int bl = idx >> 4, jj = idx & 15;
        int j = j0 + jj;
        float4 gv = *(const float4*)(const void*)&gsm[bl * 68 + jj * 4];
        float zi = gv.x + bias[j];
        float zf = gv.y + bias[512 + j];
        float zg = gv.z + bias[1024 + j];
        float zo = gv.w + bias[1536 + j];
        if (wih) {
            float xb = dins[bl];
            zi += xb * wih[j];
            zf += xb * wih[512 + j];
            zg += xb * wih[1024 + j];
            zo += xb * wih[1536 + j];
        }
        float iv = sigf(zi);
        float fv = sigf(zf);
        float gg = tanhf(zg);
        float ov = sigf(zo);
        float cc = fv * cs[bl * 16 + jj] + iv * gg;
        cs[bl * 16 + jj] = cc;
        float hh = ov * tanhf(cc);
        hdst[(size_t)(b0 + bl) * HH + j] = __float2half(hh);
    }
}

__global__ void __launch_bounds__(NTHR, 1)
lstm_persistent_kernel(const float* __restrict__ x,
                       const float* __restrict__ eWih0, const float* __restrict__ eWhh0,
                       const float* __restrict__ eb0,
                       const float* __restrict__ eWih1, const float* __restrict__ eWhh1,
                       const float* __restrict__ eb1,
                       const float* __restrict__ dWih0, const float* __restrict__ dWhh0,
                       const float* __restrict__ db0,
                       const float* __restrict__ dWih1, const float* __restrict__ dWhh1,
                       const float* __restrict__ db1,
                       const float* __restrict__ headW, const float* __restrict__ headb,
                       float* __restrict__ out) {
    extern __shared__ char smem_raw[];
    __half* Abuf = (__half*)smem_raw;                    // 4 * 128*72 halves = 73728 B
    __half* Wbuf = (__half*)(smem_raw + 73728);          // 4 * 64*72  halves = 36864 B
    float*  gsm  = (float*)(smem_raw + 110592);          // 128*68 = 34816 B
    float*  c0s  = (float*)(smem_raw + 145408);          // 8192 B
    float*  c1s  = (float*)(smem_raw + 153600);          // 8192 B
    float*  dins = (float*)(smem_raw + 161792);          // 512 B

    const int tid  = threadIdx.x;
    const int cta  = blockIdx.x;
    const int mb   = cta >> 5, nc = cta & 31;
    const int b0   = mb * 128, n0 = nc * 64, j0 = nc * 16;
    const int lane = tid & 31, warp = tid >> 5;
    const int wm   = (warp >> 2) * 32, wn = (warp & 3) * 16;
    const int grp  = lane >> 2, tig = lane & 3;
    // ldmatrix per-lane addressing
    const int a_row = lane & 15, a_k = (lane >> 4) * 8;
    const int b_row = (lane & 7) + ((lane >> 4) << 3), b_k = ((lane >> 3) & 1) * 8;

    // ---- init: convert weights fp32->fp16 with gate-interleaved row permutation ----
    {
        int gtid = cta * NTHR + tid;
        const float* wsrc[6] = {eWhh0, eWih1, eWhh1, dWhh0, dWih1, dWhh1};
#pragma unroll
        for (int m = 0; m < 6; m++) {
            for (int i = gtid; i < G4 * HH; i += NCTA * NTHR) {
                int n = i >> 9, k = i & 511;
                int j = n >> 2, g = n & 3;
                g_wh[m][i] = __float2half(wsrc[m][(size_t)(g * 512 + j) * HH + k]);
            }
        }
        for (int i = gtid; i < BB * HH; i += NCTA * NTHR) {
            g_h0[0][i] = __float2half(0.f);
            g_h1[0][i] = __float2half(0.f);
        }
        for (int i = tid; i < 128 * 16; i += NTHR) { c0s[i] = 0.f; c1s[i] = 0.f; }
    }
    grid_bar();

    for (int step = 0; step < TT + HOR; step++) {
        const bool enc = step < TT;
        const int p = step & 1;
        const __half* h0r = g_h0[p];
        __half* h0w = g_h0[p ^ 1];
        const __half* h1r = g_h1[p];
        __half* h1w = g_h1[p ^ 1];
        const int s = step - TT;

        // ---------- Phase A (layer 0) ----------
        if (tid < 128) {
            float v;
            if (enc) {
                v = x[(size_t)(b0 + tid) * TT + step];
            } else if (s == 0) {
                v = x[(size_t)(b0 + tid) * TT + (TT - 1)];
            } else {
                v = headb[0];
#pragma unroll
                for (int cc = 0; cc < 32; cc++) v += __ldcg(&g_part[cc * BB + b0 + tid]);
                if (nc == 0) out[(size_t)(b0 + tid) * HOR + (s - 1)] = v;
            }
            dins[tid] = v;
        }

        float acc[2][2][4];
#pragma unroll
        for (int a = 0; a < 2; a++)
#pragma unroll
            for (int b = 0; b < 2; b++)
#pragma unroll
                for (int c = 0; c < 4; c++) acc[a][b][c] = 0.f;

        run_gemm(acc, Abuf, Wbuf,
                 h0r, &g_wh[enc ? 0 : 3][0], h0r, &g_wh[enc ? 0 : 3][0],
                 8, b0, n0, tid, wm, wn, a_row, a_k, b_row, b_k);
        store_gates(acc, gsm, wm, wn, grp, tig);
        __syncthreads();
        pointwise(gsm, c0s, h0w, enc ? eb0 : db0, enc ? eWih0 : dWih0, dins, b0, j0, tid);
        grid_bar();

        // ---------- Phase B (layer 1): two K=512 GEMMs fused into one 16-chunk pass ----
#pragma unroll
        for (int a = 0; a < 2; a++)
#pragma unroll
            for (int b = 0; b < 2; b++)
#pragma unroll
                for (int c = 0; c < 4; c++) acc[a][b][c] = 0.f;

        run_gemm(acc, Abuf, Wbuf,
                 h0w, &g_wh[enc ? 1 : 4][0], h1r, &g_wh[enc ? 2 : 5][0],
                 16, b0, n0, tid, wm, wn, a_row, a_k, b_row, b_k);
        store_gates(acc, gsm, wm, wn, grp, tig);
        __syncthreads();
        pointwise(gsm, c1s, h1w, enc ? eb1 : db1, (const float*)0, dins, b0, j0, tid);

        if (!enc) {
            __syncthreads();
            if (tid < 128) {
                float pv = 0.f;
#pragma unroll
                for (int jj = 0; jj < 16; jj++)
                    pv += __half2float(h1w[(size_t)(b0 + tid) * HH + j0 + jj]) * headW[j0 + jj];
                g_part[nc * BB + b0 + tid] = pv;
            }
            grid_bar();   // decoder only: publish g_part (h-visibility handled by bar after phase A)
        }
    }

    // ---- epilogue: final horizon output ----
    if (nc == 0 && tid < 128) {
        float v = headb[0];
#pragma unroll
        for (int cc = 0; cc < 32; cc++) v += __ldcg(&g_part[cc * BB + b0 + tid]);
        out[(size_t)(b0 + tid) * HOR + (HOR - 1)] = v;
    }
}

extern "C" void kernel_launch(void* const* d_in, const int* in_sizes, int n_in,
                              void* d_out, int out_size) {
    cudaFuncSetAttribute(lstm_persistent_kernel,
                         cudaFuncAttributeMaxDynamicSharedMemorySize, SMEM_BYTES);
    lstm_persistent_kernel<<<NCTA, NTHR, SMEM_BYTES>>>(
        (const float*)d_in[0],
        (const float*)d_in[1], (const float*)d_in[2], (const float*)d_in[3],
        (const float*)d_in[4], (const float*)d_in[5], (const float*)d_in[6],
        (const float*)d_in[7], (const float*)d_in[8], (const float*)d_in[9],
        (const float*)d_in[10], (const float*)d_in[11], (const float*)d_in[12],
        (const float*)d_in[13], (const float*)d_in[14],
        (float*)d_out);
}

// round 4
// speedup vs baseline: 1.1294x; 1.0303x over previous
#include <cuda_runtime.h>
#include <cuda_fp16.h>
#include <stdint.h>

#define BB   512
#define TT   256
#define HHID 512
#define HOR  64
#define NCTA 128
#define NTHR 512
#define WS_BYTES    65536              /* one matrix slice: 64 rows x 512 halves */
#define RING_OFF    (3 * WS_BYTES)     /* 196608 */
#define STAGE_BYTES 16384              /* 128 rows x 64 halves (128B rows, sw<3,4,3>) */
#define DINS_OFF    (RING_OFF + 2 * STAGE_BYTES)  /* 229376 */
#define SMEM_BYTES  (DINS_OFF + 512)   /* 229888 <= 232448 */

__device__ __align__(128) __half g_h0[2][BB * HHID];
__device__ __align__(128) __half g_h1[2][BB * HHID];
__device__ float  g_part2[BB * 128];   /* [row][wslot] */
__device__ unsigned g_count = 0u;
__device__ volatile unsigned g_gen = 0u;

__device__ __forceinline__ void grid_bar() {
    __syncthreads();
    __threadfence();
    if (threadIdx.x == 0) {
        unsigned g = g_gen;
        if (atomicAdd(&g_count, 1u) == NCTA - 1) {
            g_count = 0u;
            __threadfence();
            g_gen = g + 1u;
        } else {
            while (g_gen == g) { __nanosleep(20); }
        }
        __threadfence();
    }
    __syncthreads();
}

__device__ __forceinline__ void cpa16(uint32_t dst, const void* src) {
    asm volatile("cp.async.cg.shared.global [%0], [%1], 16;\n" :: "r"(dst), "l"(src));
}
__device__ __forceinline__ void ldsm4(uint32_t* r, uint32_t a) {
    asm volatile("ldmatrix.sync.aligned.m8n8.x4.shared.b16 {%0,%1,%2,%3}, [%4];\n"
                 : "=r"(r[0]), "=r"(r[1]), "=r"(r[2]), "=r"(r[3]) : "r"(a));
}
#define MMA(d, A, B0, B1)                                                      \
    asm volatile("mma.sync.aligned.m16n8k16.row.col.f32.f16.f16.f32 "          \
                 "{%0,%1,%2,%3},{%4,%5,%6,%7},{%8,%9},{%0,%1,%2,%3};"          \
                 : "+f"(d[0]), "+f"(d[1]), "+f"(d[2]), "+f"(d[3])              \
                 : "r"(A[0]), "r"(A[1]), "r"(A[2]), "r"(A[3]), "r"(B0), "r"(B1))

// stage one K-chunk of 64 (128 rows x 128B) into ring buffer `buf`
__device__ __forceinline__ void stage64(uint32_t ring, int buf, const __half* hsrc,
                                        int b0, int kc, int tid) {
    uint32_t base = ring + buf * STAGE_BYTES;
#pragma unroll
    for (int u = 0; u < 2; u++) {
        int i = tid + u * NTHR;
        int lr = i >> 3, cb = i & 7;
        cpa16(base + lr * 128 + (((cb ^ (lr & 7)) << 4)),
              hsrc + (size_t)(b0 + lr) * HHID + kc + cb * 8);
    }
    asm volatile("cp.async.commit_group;\n" ::: "memory");
}

// one K=64 chunk of MMAs: acc += A(128x64) @ W(64x64)^T for this warp's 32x16 tile
__device__ __forceinline__ void mma_chunk(float acc[2][2][4],
                                          uint32_t Ast, uint32_t Wmat, int chW,
                                          int wm, int wn, int lane) {
    const int a_row = lane & 15, akc = lane >> 4;
    const int b_row = (lane & 7) + ((lane >> 4) << 3), bkc = (lane >> 3) & 1;
    const int R = wn + b_row, R7 = R & 7;
    const uint32_t Wrow = Wmat + R * 1024;
    const int lr0 = wm + a_row;
    const int l07 = lr0 & 7;
    const uint32_t Ar0 = Ast + lr0 * 128, Ar1 = Ar0 + 16 * 128;
#pragma unroll
    for (int kk = 0; kk < 64; kk += 16) {
        int kc8 = kk >> 3;
        uint32_t Bf[4], A0[4], A1[4];
        ldsm4(Bf, Wrow + ((((chW * 8 + kc8 + bkc) ^ R7)) << 4));
        int ca = (kc8 + akc) ^ l07;
        ldsm4(A0, Ar0 + (ca << 4));
        ldsm4(A1, Ar1 + (ca << 4));
        MMA(acc[0][0], A0, Bf[0], Bf[1]);
        MMA(acc[0][1], A0, Bf[2], Bf[3]);
        MMA(acc[1][0], A1, Bf[0], Bf[1]);
        MMA(acc[1][1], A1, Bf[2], Bf[3]);
    }
}

// full GEMM phase: nch chunks of K=64; chunks >=8 switch A source & W matrix
__device__ __forceinline__ void run_phase(float acc[2][2][4],
                                          uint32_t ring, uint32_t ws0, uint32_t ws1,
                                          const __half* a0src, const __half* a1src,
                                          int nch, int b0, int tid,
                                          int wm, int wn, int lane) {
    __syncthreads();                       // ring safe to overwrite
    stage64(ring, 0, a0src, b0, 0, tid);
    stage64(ring, 1, a0src, b0, 64, tid);
#pragma unroll 1
    for (int ch = 0; ch < nch; ch++) {
        if (ch + 1 < nch) asm volatile("cp.async.wait_group 1;\n" ::: "memory");
        else              asm volatile("cp.async.wait_group 0;\n" ::: "memory");
        __syncthreads();
        mma_chunk(acc, ring + (ch & 1) * STAGE_BYTES,
                  (ch < 8) ? ws0 : ws1, ch & 7, wm, wn, lane);
        __syncthreads();
        int pf = ch + 2;
        if (pf < nch)
            stage64(ring, pf & 1, (pf < 8) ? a0src : a1src, b0, (pf & 7) * 64, tid);
    }
}

// convert 3 weight matrices' 64-row slices fp32 -> fp16 into swizzled smem
__device__ void load_weights(char* smem, const float* w0, const float* w1,
                             const float* w2, int n0, int tid) {
    const float* ws[3] = {w0, w1, w2};
#pragma unroll
    for (int m = 0; m < 3; m++) {
        for (int i = tid; i < 64 * 512; i += NTHR) {
            int r = i >> 9, k = i & 511;
            int pr = n0 + r, j = pr >> 2, g = pr & 3;
            float v = ws[m][(size_t)(g * 512 + j) * HHID + k];
            int ck = k >> 3;
            int off = m * WS_BYTES + r * 1024 + (((ck ^ (r & 7)) << 4)) + (k & 7) * 2;
            *(__half*)(smem + off) = __float2half(v);
        }
    }
}

__device__ __forceinline__ void load_gv(float d[2][4], const float* b, int u0, int u1) {
    d[0][0] = b[u0]; d[0][1] = b[512 + u0]; d[0][2] = b[1024 + u0]; d[0][3] = b[1536 + u0];
    d[1][0] = b[u1]; d[1][1] = b[512 + u1]; d[1][2] = b[1024 + u1]; d[1][3] = b[1536 + u1];
}

__device__ __forceinline__ float sigf(float z) { return 1.f / (1.f + __expf(-z)); }

// in-register LSTM pointwise on MMA fragments (gate layout: col = 4*unit + gate)
__device__ __forceinline__ void pointwise_frag(
    float acc[2][2][4], float* cst,
    const float bv[2][4], const float wv[2][4], bool use_w,
    const float* dins, int wm, int grp, int lane, bool even,
    __half* hout, int b0, const int* u2,
    bool do_head, const float* hw, int wslot) {
    const unsigned FULL = 0xFFFFFFFFu;
    float pv[4] = {0.f, 0.f, 0.f, 0.f};
#pragma unroll
    for (int mf = 0; mf < 2; mf++) {
        int r1 = wm + mf * 16 + grp;
        float v1 = 0.f, v2 = 0.f;
        if (use_w) { v1 = dins[r1]; v2 = dins[r1 + 8]; }
#pragma unroll
        for (int nf = 0; nf < 2; nf++) {
            float g1 = __shfl_xor_sync(FULL, acc[mf][nf][0], 1);
            float o1 = __shfl_xor_sync(FULL, acc[mf][nf][1], 1);
            float g2 = __shfl_xor_sync(FULL, acc[mf][nf][2], 1);
            float o2 = __shfl_xor_sync(FULL, acc[mf][nf][3], 1);
            if (even) {
                float zi1 = acc[mf][nf][0] + bv[nf][0];
                float zf1 = acc[mf][nf][1] + bv[nf][1];
                float zg1 = g1 + bv[nf][2];
                float zo1 = o1 + bv[nf][3];
                float zi2 = acc[mf][nf][2] + bv[nf][0];
                float zf2 = acc[mf][nf][3] + bv[nf][1];
                float zg2 = g2 + bv[nf][2];
                float zo2 = o2 + bv[nf][3];
                if (use_w) {
                    zi1 += v1 * wv[nf][0]; zf1 += v1 * wv[nf][1];
                    zg1 += v1 * wv[nf][2]; zo1 += v1 * wv[nf][3];
                    zi2 += v2 * wv[nf][0]; zf2 += v2 * wv[nf][1];
                    zg2 += v2 * wv[nf][2]; zo2 += v2 * wv[nf][3];
                }
                int ci = mf * 4 + nf * 2;
                float c1 = sigf(zf1) * cst[ci]     + sigf(zi1) * tanhf(zg1);
                float c2 = sigf(zf2) * cst[ci + 1] + sigf(zi2) * tanhf(zg2);
                cst[ci] = c1; cst[ci + 1] = c2;
                float h1 = sigf(zo1) * tanhf(c1);
                float h2 = sigf(zo2) * tanhf(c2);
                hout[(size_t)(b0 + r1) * HHID + u2[nf]]     = __float2half(h1);
                hout[(size_t)(b0 + r1 + 8) * HHID + u2[nf]] = __float2half(h2);
                if (do_head) {
                    pv[mf * 2]     += h1 * hw[nf];
                    pv[mf * 2 + 1] += h2 * hw[nf];
                }
            }
        }
    }
    if (do_head) {
#pragma unroll
        for (int q = 0; q < 4; q++) {
            float s = pv[q] + __shfl_xor_sync(FULL, pv[q], 2);
            if (even && (lane & 2) == 0) {
                int row = wm + (q >> 1) * 16 + grp + (q & 1) * 8;
                g_part2[(size_t)(b0 + row) * 128 + wslot] = s;
            }
        }
    }
}

__global__ void __launch_bounds__(NTHR, 1)
lstm_persistent_kernel(const float* __restrict__ x,
                       const float* __restrict__ eWih0, const float* __restrict__ eWhh0,
                       const float* __restrict__ eb0,
                       const float* __restrict__ eWih1, const float* __restrict__ eWhh1,
                       const float* __restrict__ eb1,
                       const float* __restrict__ dWih0, const float* __restrict__ dWhh0,
                       const float* __restrict__ db0,
                       const float* __restrict__ dWih1, const float* __restrict__ dWhh1,
                       const float* __restrict__ db1,
                       const float* __restrict__ headW, const float* __restrict__ headb,
                       float* __restrict__ out) {
    extern __shared__ __align__(1024) char smem[];
    uint32_t sb;
    asm("{ .reg .u64 t; cvta.to.shared.u64 t, %1; cvt.u32.u64 %0, t; }"
        : "=r"(sb) : "l"(smem));
    const uint32_t ws0 = sb, ws1 = sb + WS_BYTES, ws2 = sb + 2 * WS_BYTES;
    const uint32_t ring = sb + RING_OFF;
    float* dins = (float*)(smem + DINS_OFF);

    const int tid  = threadIdx.x;
    const int lane = tid & 31, warp = tid >> 5;
    const int cta  = blockIdx.x;
    const int mb   = cta >> 5, nc = cta & 31;
    const int b0   = mb * 128, n0 = nc * 64;
    const int wm   = (warp >> 2) * 32, wn = (warp & 3) * 16;
    const int grp  = lane >> 2, tig = lane & 3;
    const bool even = (tig & 1) == 0;
    const int wslot = nc * 4 + (warp & 3);

    // per-lane hidden-unit indices (even lanes): units ubase, ubase+2
    const int ubase = ((n0 + wn) >> 2) + (tig >> 1);
    int u2[2] = {ubase, ubase + 2};

    // ---- init: encoder weights into smem, zero h, preload per-lane constants ----
    load_weights(smem, eWhh0, eWih1, eWhh1, n0, tid);
    {
        int gtid = cta * NTHR + tid;
        for (int i = gtid; i < BB * HHID; i += NCTA * NTHR) {
            g_h0[0][i] = __float2half(0.f);
            g_h1[0][i] = __float2half(0.f);
        }
    }
    float bL0[2][4], wL0[2][4], bL1[2][4], hw[2];
    load_gv(bL0, eb0, u2[0], u2[1]);
    load_gv(wL0, eWih0, u2[0], u2[1]);
    load_gv(bL1, eb1, u2[0], u2[1]);
    hw[0] = headW[u2[0]]; hw[1] = headW[u2[1]];
    const float hb = headb[0];

    float c0st[8], c1st[8];
#pragma unroll
    for (int i = 0; i < 8; i++) { c0st[i] = 0.f; c1st[i] = 0.f; }

    grid_bar();

    for (int step = 0; step < TT + HOR; step++) {
        const bool enc = step < TT;
        const int p = step & 1;
        const int s = step - TT;
        const __half* h0r = g_h0[p];
        __half* h0w = g_h0[p ^ 1];
        const __half* h1r = g_h1[p];
        __half* h1w = g_h1[p ^ 1];

        if (step == TT) {   // switch to decoder weights (smem is per-CTA)
            __syncthreads();
            load_weights(smem, dWhh0, dWih1, dWhh1, n0, tid);
            load_gv(bL0, db0, u2[0], u2[1]);
            load_gv(wL0, dWih0, u2[0], u2[1]);
            load_gv(bL1, db1, u2[0], u2[1]);
            __syncthreads();
        }

        // ---- input fill ----
        if (tid < 128) {
            float v;
            if (enc) {
                v = x[(size_t)(b0 + tid) * TT + step];
            } else if (s == 0) {
                v = x[(size_t)(b0 + tid) * TT + (TT - 1)];
            } else {
                v = hb;
                const float4* gp = (const float4*)(g_part2 + (size_t)(b0 + tid) * 128);
#pragma unroll
                for (int q = 0; q < 32; q++) {
                    float4 t = __ldcg(&gp[q]);
                    v += t.x + t.y + t.z + t.w;
                }
                if (nc == 0) out[(size_t)(b0 + tid) * HOR + (s - 1)] = v;
            }
            dins[tid] = v;
        }

        // ---------- Phase A (layer 0), K=512 ----------
        float acc[2][2][4];
#pragma unroll
        for (int a = 0; a < 2; a++)
#pragma unroll
            for (int b = 0; b < 2; b++)
#pragma unroll
                for (int c = 0; c < 4; c++) acc[a][b][c] = 0.f;
        run_phase(acc, ring, ws0, ws0, h0r, h0r, 8, b0, tid, wm, wn, lane);
        pointwise_frag(acc, c0st, bL0, wL0, true, dins, wm, grp, lane, even,
                       h0w, b0, u2, false, hw, wslot);
        grid_bar();

        // ---------- Phase B (layer 1), K=1024 fused ----------
#pragma unroll
        for (int a = 0; a < 2; a++)
#pragma unroll
            for (int b = 0; b < 2; b++)
#pragma unroll
                for (int c = 0; c < 4; c++) acc[a][b][c] = 0.f;
        run_phase(acc, ring, ws1, ws2, h0w, h1r, 16, b0, tid, wm, wn, lane);
        pointwise_frag(acc, c1st, bL1, wL0, false, dins, wm, grp, lane, even,
                       h1w, b0, u2, !enc, hw, wslot);
        if (!enc) grid_bar();
    }

    // ---- final horizon output ----
    if (nc == 0 && tid < 128) {
        float v = hb;
        const float4* gp = (const float4*)(g_part2 + (size_t)(b0 + tid) * 128);
#pragma unroll
        for (int q = 0; q < 32; q++) {
            float4 t = __ldcg(&gp[q]);
            v += t.x + t.y + t.z + t.w;
        }
        out[(size_t)(b0 + tid) * HOR + (HOR - 1)] = v;
    }
}

extern "C" void kernel_launch(void* const* d_in, const int* in_sizes, int n_in,
                              void* d_out, int out_size) {
    cudaFuncSetAttribute(lstm_persistent_kernel,
                         cudaFuncAttributeMaxDynamicSharedMemorySize, SMEM_BYTES);
    lstm_persistent_kernel<<<NCTA, NTHR, SMEM_BYTES>>>(
        (const float*)d_in[0],
        (const float*)d_in[1], (const float*)d_in[2], (const float*)d_in[3],
        (const float*)d_in[4], (const float*)d_in[5], (const float*)d_in[6],
        (const float*)d_in[7], (const float*)d_in[8], (const float*)d_in[9],
        (const float*)d_in[10], (const float*)d_in[11], (const float*)d_in[12],
        (const float*)d_in[13], (const float*)d_in[14],
        (float*)d_out);
}

// round 5
// speedup vs baseline: 1.3777x; 1.2199x over previous
#include <cuda_runtime.h>
#include <cuda_fp16.h>
#include <stdint.h>

#define BB   512
#define TT   256
#define HHID 512
#define HOR  64
#define NCTA 128
#define NTHR 256
#define WS_BYTES    65536              /* one matrix slice: 64 rows x 512 halves */
#define RING_OFF    (3 * WS_BYTES)     /* 196608 */
#define STAGE_BYTES 16384              /* 128 rows x 64 halves (128B rows, sw) */
#define DINS_OFF    (RING_OFF + 2 * STAGE_BYTES)  /* 229376 */
#define SMEM_BYTES  (DINS_OFF + 512)   /* 229888 */

__device__ __align__(128) __half g_h0[2][BB * HHID];
__device__ __align__(128) __half g_h1[2][BB * HHID];
__device__ float  g_part2[BB * 64];    /* [row][slot], slot = nc*2 + (warp&1) */
__device__ unsigned g_count = 0u;
__device__ volatile unsigned g_gen = 0u;

__device__ __forceinline__ void grid_bar() {
    __syncthreads();
    __threadfence();
    if (threadIdx.x == 0) {
        unsigned g = g_gen;
        if (atomicAdd(&g_count, 1u) == NCTA - 1) {
            g_count = 0u;
            __threadfence();
            g_gen = g + 1u;
        } else {
            while (g_gen == g) { }
        }
        __threadfence();
    }
    __syncthreads();
}

__device__ __forceinline__ void cpa16(uint32_t dst, const void* src) {
    asm volatile("cp.async.cg.shared.global [%0], [%1], 16;\n" :: "r"(dst), "l"(src));
}
__device__ __forceinline__ void ldsm4(uint32_t* r, uint32_t a) {
    asm volatile("ldmatrix.sync.aligned.m8n8.x4.shared.b16 {%0,%1,%2,%3}, [%4];\n"
                 : "=r"(r[0]), "=r"(r[1]), "=r"(r[2]), "=r"(r[3]) : "r"(a));
}
#define MMA(d, A, B0, B1)                                                      \
    asm volatile("mma.sync.aligned.m16n8k16.row.col.f32.f16.f16.f32 "          \
                 "{%0,%1,%2,%3},{%4,%5,%6,%7},{%8,%9},{%0,%1,%2,%3};"          \
                 : "+f"(d[0]), "+f"(d[1]), "+f"(d[2]), "+f"(d[3])              \
                 : "r"(A[0]), "r"(A[1]), "r"(A[2]), "r"(A[3]), "r"(B0), "r"(B1))

// stage one K-chunk of 64 (128 rows x 128B swizzled) into ring buffer `buf`
__device__ __forceinline__ void stage64(uint32_t ring, int buf, const __half* hsrc,
                                        int b0, int kc, int tid) {
    uint32_t base = ring + buf * STAGE_BYTES;
#pragma unroll
    for (int u = 0; u < 4; u++) {
        int i = tid + u * NTHR;              // 0..1023
        int lr = i >> 3, cb = i & 7;
        cpa16(base + lr * 128 + (((cb ^ (lr & 7)) << 4)),
              hsrc + (size_t)(b0 + lr) * HHID + kc + cb * 8);
    }
    asm volatile("cp.async.commit_group;\n" ::: "memory");
}

// one K=64 chunk: acc += A(128x64) @ W(64x64)^T, warp tile 32(M) x 32(N)
__device__ __forceinline__ void mma_chunk(float acc[2][4][4],
                                          uint32_t Ast, uint32_t Wmat, int chW,
                                          int wm, int wn, int lane) {
    const int a_row = lane & 15, akc = lane >> 4;
    const int b_row = (lane & 7) + ((lane >> 4) << 3), bkc = (lane >> 3) & 1;
    const int R0 = wn + b_row, R1 = wn + 16 + b_row;
    const uint32_t Wr0 = Wmat + R0 * 1024, Wr1 = Wmat + R1 * 1024;
    const int R07 = R0 & 7, R17 = R1 & 7;
    const int lr0 = wm + a_row, l07 = lr0 & 7;
    const uint32_t Ar0 = Ast + lr0 * 128, Ar1 = Ar0 + 16 * 128;
#pragma unroll
    for (int kk = 0; kk < 64; kk += 16) {
        int kc8 = kk >> 3;
        uint32_t Ba[4], Bb[4], A0[4], A1[4];
        int cb = chW * 8 + kc8 + bkc;
        ldsm4(Ba, Wr0 + (((cb ^ R07)) << 4));
        ldsm4(Bb, Wr1 + (((cb ^ R17)) << 4));
        int ca = (kc8 + akc) ^ l07;
        ldsm4(A0, Ar0 + (ca << 4));
        ldsm4(A1, Ar1 + (ca << 4));
        MMA(acc[0][0], A0, Ba[0], Ba[1]);
        MMA(acc[0][1], A0, Ba[2], Ba[3]);
        MMA(acc[0][2], A0, Bb[0], Bb[1]);
        MMA(acc[0][3], A0, Bb[2], Bb[3]);
        MMA(acc[1][0], A1, Ba[0], Ba[1]);
        MMA(acc[1][1], A1, Ba[2], Ba[3]);
        MMA(acc[1][2], A1, Bb[0], Bb[1]);
        MMA(acc[1][3], A1, Bb[2], Bb[3]);
    }
}

// full GEMM phase: nch K=64 chunks, ONE barrier per chunk, 2-buffer ring
__device__ __forceinline__ void run_phase(float acc[2][4][4],
                                          uint32_t ring, uint32_t ws0, uint32_t ws1,
                                          const __half* a0src, const __half* a1src,
                                          int nch, int b0, int tid,
                                          int wm, int wn, int lane) {
    stage64(ring, 0, a0src, b0, 0, tid);
#pragma unroll 1
    for (int ch = 0; ch < nch; ch++) {
        asm volatile("cp.async.wait_group 0;\n" ::: "memory");
        __syncthreads();
        int pf = ch + 1;
        if (pf < nch)
            stage64(ring, pf & 1, (pf < 8) ? a0src : a1src, b0, (pf & 7) * 64, tid);
        mma_chunk(acc, ring + (ch & 1) * STAGE_BYTES,
                  (ch < 8) ? ws0 : ws1, ch & 7, wm, wn, lane);
    }
}

// convert 3 weight matrices' 64-row slices fp32 -> fp16 into swizzled smem
__device__ void load_weights(char* smem, const float* w0, const float* w1,
                             const float* w2, int n0, int tid) {
    const float* ws[3] = {w0, w1, w2};
#pragma unroll
    for (int m = 0; m < 3; m++) {
        for (int i = tid; i < 64 * 512; i += NTHR) {
            int r = i >> 9, k = i & 511;
            int pr = n0 + r, j = pr >> 2, g = pr & 3;
            float v = ws[m][(size_t)(g * 512 + j) * HHID + k];
            int ck = k >> 3;
            int off = m * WS_BYTES + r * 1024 + (((ck ^ (r & 7)) << 4)) + (k & 7) * 2;
            *(__half*)(smem + off) = __float2half(v);
        }
    }
}

__device__ __forceinline__ void load_gv(float d[2][4], const float* b, int u0, int u1) {
    d[0][0] = b[u0]; d[0][1] = b[512 + u0]; d[0][2] = b[1024 + u0]; d[0][3] = b[1536 + u0];
    d[1][0] = b[u1]; d[1][1] = b[512 + u1]; d[1][2] = b[1024 + u1]; d[1][3] = b[1536 + u1];
}

__device__ __forceinline__ float sigf(float z) { return 0.5f * tanhf(0.5f * z) + 0.5f; }

// balanced in-register LSTM pointwise (all lanes active; nf-parity split)
__device__ __forceinline__ void pointwise_frag(
    float acc[2][4][4], float* cst,
    const float bv[2][4], const float wv[2][4], bool use_w,
    const float* dins, int wm, int grp, int tig,
    __half* hout, int b0, const int* ug,
    bool do_head, const float* hw, int slot) {
    const unsigned FULL = 0xFFFFFFFFu;
    float pv[4] = {0.f, 0.f, 0.f, 0.f};
#pragma unroll
    for (int mf = 0; mf < 2; mf++) {
        int r0 = wm + mf * 16 + grp;
        float va = use_w ? dins[r0] : 0.f;
        float vb = use_w ? dins[r0 + 8] : 0.f;
#pragma unroll
        for (int nf = 0; nf < 4; nf++) {
            float e0 = __shfl_xor_sync(FULL, acc[mf][nf][0], 1);
            float e1 = __shfl_xor_sync(FULL, acc[mf][nf][1], 1);
            float e2 = __shfl_xor_sync(FULL, acc[mf][nf][2], 1);
            float e3 = __shfl_xor_sync(FULL, acc[mf][nf][3], 1);
            if (((nf ^ tig) & 1) == 0) {
                int no = nf >> 1;
                float zi0, zf0, zg0, zo0, zi1, zf1, zg1, zo1;
                if ((tig & 1) == 0) {
                    zi0 = acc[mf][nf][0]; zf0 = acc[mf][nf][1]; zg0 = e0; zo0 = e1;
                    zi1 = acc[mf][nf][2]; zf1 = acc[mf][nf][3]; zg1 = e2; zo1 = e3;
                } else {
                    zg0 = acc[mf][nf][0]; zo0 = acc[mf][nf][1]; zi0 = e0; zf0 = e1;
                    zg1 = acc[mf][nf][2]; zo1 = acc[mf][nf][3]; zi1 = e2; zf1 = e3;
                }
                zi0 += bv[no][0]; zf0 += bv[no][1]; zg0 += bv[no][2]; zo0 += bv[no][3];
                zi1 += bv[no][0]; zf1 += bv[no][1]; zg1 += bv[no][2]; zo1 += bv[no][3];
                if (use_w) {
                    zi0 += va * wv[no][0]; zf0 += va * wv[no][1];
                    zg0 += va * wv[no][2]; zo0 += va * wv[no][3];
                    zi1 += vb * wv[no][0]; zf1 += vb * wv[no][1];
                    zg1 += vb * wv[no][2]; zo1 += vb * wv[no][3];
                }
                int ci = mf * 4 + no * 2;
                float cA = sigf(zf0) * cst[ci]     + sigf(zi0) * tanhf(zg0);
                float cB = sigf(zf1) * cst[ci + 1] + sigf(zi1) * tanhf(zg1);
                cst[ci] = cA; cst[ci + 1] = cB;
                float hA = sigf(zo0) * tanhf(cA);
                float hB = sigf(zo1) * tanhf(cB);
                hout[(size_t)(b0 + r0) * HHID + ug[no]]     = __float2half(hA);
                hout[(size_t)(b0 + r0 + 8) * HHID + ug[no]] = __float2half(hB);
                if (do_head) {
                    pv[mf * 2]     += hA * hw[no];
                    pv[mf * 2 + 1] += hB * hw[no];
                }
            }
        }
    }
    if (do_head) {
#pragma unroll
        for (int q = 0; q < 4; q++) {
            float s = pv[q] + __shfl_xor_sync(FULL, pv[q], 1);
            s += __shfl_xor_sync(FULL, s, 2);
            if (tig == 0) {
                int row = wm + (q >> 1) * 16 + grp + (q & 1) * 8;
                g_part2[(size_t)(b0 + row) * 64 + slot] = s;
            }
        }
    }
}

__global__ void __launch_bounds__(NTHR, 1)
lstm_persistent_kernel(const float* __restrict__ x,
                       const float* __restrict__ eWih0, const float* __restrict__ eWhh0,
                       const float* __restrict__ eb0,
                       const float* __restrict__ eWih1, const float* __restrict__ eWhh1,
                       const float* __restrict__ eb1,
                       const float* __restrict__ dWih0, const float* __restrict__ dWhh0,
                       const float* __restrict__ db0,
                       const float* __restrict__ dWih1, const float* __restrict__ dWhh1,
                       const float* __restrict__ db1,
                       const float* __restrict__ headW, const float* __restrict__ headb,
                       float* __restrict__ out) {
    extern __shared__ __align__(1024) char smem[];
    uint32_t sb;
    asm("{ .reg .u64 t; cvta.to.shared.u64 t, %1; cvt.u32.u64 %0, t; }"
        : "=r"(sb) : "l"(smem));
    const uint32_t ws0 = sb, ws1 = sb + WS_BYTES, ws2 = sb + 2 * WS_BYTES;
    const uint32_t ring = sb + RING_OFF;
    float* dins = (float*)(smem + DINS_OFF);

    const int tid  = threadIdx.x;
    const int lane = tid & 31, warp = tid >> 5;
    const int cta  = blockIdx.x;
    const int mb   = cta >> 5, nc = cta & 31;
    const int b0   = mb * 128, n0 = nc * 64;
    const int wm   = (warp >> 1) * 32, wn = (warp & 1) * 32;
    const int grp  = lane >> 2, tig = lane & 3;
    const int slot = nc * 2 + (warp & 1);

    // per-lane owned hidden units (global indices)
    int ug[2];
    ug[0] = nc * 16 + (wn >> 2) + ((tig & 1) ? 2 : 0) + (tig >> 1);
    ug[1] = ug[0] + 4;

    // ---- init ----
    load_weights(smem, eWhh0, eWih1, eWhh1, n0, tid);
    {
        int gtid = cta * NTHR + tid;
        for (int i = gtid; i < BB * HHID; i += NCTA * NTHR) {
            g_h0[0][i] = __float2half(0.f);
            g_h1[0][i] = __float2half(0.f);
        }
    }
    float bL0[2][4], wL0[2][4], bL1[2][4], hw[2];
    load_gv(bL0, eb0, ug[0], ug[1]);
    load_gv(wL0, eWih0, ug[0], ug[1]);
    load_gv(bL1, eb1, ug[0], ug[1]);
    hw[0] = headW[ug[0]]; hw[1] = headW[ug[1]];
    const float hb = headb[0];

    float c0st[8], c1st[8];
#pragma unroll
    for (int i = 0; i < 8; i++) { c0st[i] = 0.f; c1st[i] = 0.f; }

    grid_bar();

    for (int step = 0; step < TT + HOR; step++) {
        const bool enc = step < TT;
        const int p = step & 1;
        const int s = step - TT;
        const __half* h0r = g_h0[p];
        __half* h0w = g_h0[p ^ 1];
        const __half* h1r = g_h1[p];
        __half* h1w = g_h1[p ^ 1];

        if (step == TT) {   // switch to decoder weights
            __syncthreads();
            load_weights(smem, dWhh0, dWih1, dWhh1, n0, tid);
            load_gv(bL0, db0, ug[0], ug[1]);
            load_gv(wL0, dWih0, ug[0], ug[1]);
            load_gv(bL1, db1, ug[0], ug[1]);
            __syncthreads();
        }

        // ---- input fill ----
        if (tid < 128) {
            float v;
            if (enc) {
                v = x[(size_t)(b0 + tid) * TT + step];
            } else if (s == 0) {
                v = x[(size_t)(b0 + tid) * TT + (TT - 1)];
            } else {
                v = hb;
                const float4* gp = (const float4*)(g_part2 + (size_t)(b0 + tid) * 64);
#pragma unroll
                for (int q = 0; q < 16; q++) {
                    float4 t = __ldcg(&gp[q]);
                    v += t.x + t.y + t.z + t.w;
                }
                if (nc == 0) out[(size_t)(b0 + tid) * HOR + (s - 1)] = v;
            }
            dins[tid] = v;
        }

        // ---------- Phase A (layer 0), K=512 ----------
        float acc[2][4][4];
#pragma unroll
        for (int a = 0; a < 2; a++)
#pragma unroll
            for (int b = 0; b < 4; b++)
#pragma unroll
                for (int c = 0; c < 4; c++) acc[a][b][c] = 0.f;
        run_phase(acc, ring, ws0, ws0, h0r, h0r, 8, b0, tid, wm, wn, lane);
        pointwise_frag(acc, c0st, bL0, wL0, true, dins, wm, grp, tig,
                       h0w, b0, ug, false, hw, slot);
        grid_bar();

        // ---------- Phase B (layer 1), K=1024 fused ----------
#pragma unroll
        for (int a = 0; a < 2; a++)
#pragma unroll
            for (int b = 0; b < 4; b++)
#pragma unroll
                for (int c = 0; c < 4; c++) acc[a][b][c] = 0.f;
        run_phase(acc, ring, ws1, ws2, h0w, h1r, 16, b0, tid, wm, wn, lane);
        pointwise_frag(acc, c1st, bL1, wL0, false, dins, wm, grp, tig,
                       h1w, b0, ug, !enc, hw, slot);
        if (!enc) grid_bar();
    }

    // ---- final horizon output ----
    if (nc == 0 && tid < 128) {
        float v = hb;
        const float4* gp = (const float4*)(g_part2 + (size_t)(b0 + tid) * 64);
#pragma unroll
        for (int q = 0; q < 16; q++) {
            float4 t = __ldcg(&gp[q]);
            v += t.x + t.y + t.z + t.w;
        }
        out[(size_t)(b0 + tid) * HOR + (HOR - 1)] = v;
    }
}

extern "C" void kernel_launch(void* const* d_in, const int* in_sizes, int n_in,
                              void* d_out, int out_size) {
    cudaFuncSetAttribute(lstm_persistent_kernel,
                         cudaFuncAttributeMaxDynamicSharedMemorySize, SMEM_BYTES);
    lstm_persistent_kernel<<<NCTA, NTHR, SMEM_BYTES>>>(
        (const float*)d_in[0],
        (const float*)d_in[1], (const float*)d_in[2], (const float*)d_in[3],
        (const float*)d_in[4], (const float*)d_in[5], (const float*)d_in[6],
        (const float*)d_in[7], (const float*)d_in[8], (const float*)d_in[9],
        (const float*)d_in[10], (const float*)d_in[11], (const float*)d_in[12],
        (const float*)d_in[13], (const float*)d_in[14],
        (float*)d_out);
}